// round 2
// baseline (speedup 1.0000x reference)
#include <cuda_runtime.h>
#include <math.h>

#define B_  4
#define C_  512
#define HW  4096
#define G_  32
#define CPG 16

// Scratch (allocation-free rule: __device__ globals)
__device__ float g_hn[(size_t)B_ * C_ * HW];
__device__ float g_q [(size_t)B_ * C_ * HW];
__device__ float g_k [(size_t)B_ * C_ * HW];
__device__ float g_v [(size_t)B_ * C_ * HW];
__device__ float g_o [(size_t)B_ * C_ * HW];
__device__ float g_s [(size_t)B_ * HW * HW];   // 256 MB scores

// ---------------------------------------------------------------------------
// GroupNorm: one block per (batch, group). Group data is contiguous (16 ch * 4096).
// ---------------------------------------------------------------------------
__global__ void __launch_bounds__(256) gn_kernel(const float* __restrict__ x,
                                                 const float* __restrict__ gw,
                                                 const float* __restrict__ gb)
{
    const int bg = blockIdx.x;          // 0..127
    const int b = bg / G_, g = bg % G_;
    const size_t base = ((size_t)b * C_ + (size_t)g * CPG) * HW;
    const float* xp = x + base;
    float* op = g_hn + base;
    const int NELE = CPG * HW;          // 65536
    const int tid = threadIdx.x;

    float s = 0.f, ss = 0.f;
    for (int i = tid; i < NELE; i += 256) {
        float v = xp[i];
        s += v; ss += v * v;
    }
    __shared__ float shs[8], shss[8];
    #pragma unroll
    for (int o = 16; o; o >>= 1) {
        s  += __shfl_down_sync(0xffffffffu, s,  o);
        ss += __shfl_down_sync(0xffffffffu, ss, o);
    }
    if ((tid & 31) == 0) { shs[tid >> 5] = s; shss[tid >> 5] = ss; }
    __syncthreads();
    __shared__ float s_mu, s_rs;
    if (tid == 0) {
        float S = 0.f, SS = 0.f;
        #pragma unroll
        for (int i = 0; i < 8; i++) { S += shs[i]; SS += shss[i]; }
        float mu  = S / (float)NELE;
        float var = SS / (float)NELE - mu * mu;
        s_mu = mu;
        s_rs = rsqrtf(var + 1e-6f);
    }
    __syncthreads();
    const float mu = s_mu, rs = s_rs;
    for (int i = tid; i < NELE; i += 256) {
        int ch = g * CPG + (i >> 12);   // i / 4096
        op[i] = (xp[i] - mu) * rs * gw[ch] + gb[ch];
    }
}

// ---------------------------------------------------------------------------
// Tiled SGEMM, 64x64 tile, BK=16, 256 threads, 4x4 microtile.
// MODE 0: C = A(MxK) * B(KxN)          (NN)
// MODE 1: C = A(KxM)^T * B(KxN)        (TN)
// MODE 2: C = A(MxK) * B(NxK)^T        (NT)
// C is MxN row-major. Optional per-row bias and residual add. alpha scales A*B.
// Requires M%64==0, N%64==0, K%16==0 (true for all calls here).
// ---------------------------------------------------------------------------
#define BM 64
#define BN 64
#define BK 16

template<int MODE, bool HAS_BIAS, bool HAS_RES>
__global__ void __launch_bounds__(256) gemm_kernel(
    const float* __restrict__ A, const float* __restrict__ B,
    float* __restrict__ C, const float* __restrict__ bias,
    const float* __restrict__ res,
    int M, int N, int K,
    long sA, long sB, long sC, float alpha)
{
    const int bz = blockIdx.z;
    A += (size_t)bz * sA;
    B += (size_t)bz * sB;
    C += (size_t)bz * sC;
    if (HAS_RES) res += (size_t)bz * sC;

    __shared__ float As[BK][BM];
    __shared__ float Bs[BK][BN];

    const int tid = threadIdx.x;
    const int m0 = blockIdx.y * BM;
    const int n0 = blockIdx.x * BN;
    const int tx = tid & 15;
    const int ty = tid >> 4;

    float acc[4][4] = {};

    for (int k0 = 0; k0 < K; k0 += BK) {
        // ---- load A tile ----
        if (MODE == 0 || MODE == 2) {
            // A: MxK, lda=K, tile BM x BK, store transposed
            int r = tid >> 2;            // 0..63
            int c = (tid & 3) * 4;       // 0,4,8,12
            float4 a = *(const float4*)(A + (size_t)(m0 + r) * K + k0 + c);
            As[c + 0][r] = a.x; As[c + 1][r] = a.y;
            As[c + 2][r] = a.z; As[c + 3][r] = a.w;
        } else {
            // TN: A is KxM, lda=M, tile BK x BM
            int r = tid >> 4;            // 0..15
            int c = (tid & 15) * 4;      // 0..60
            float4 a = *(const float4*)(A + (size_t)(k0 + r) * M + m0 + c);
            *(float4*)&As[r][c] = a;
        }
        // ---- load B tile ----
        if (MODE == 0 || MODE == 1) {
            // B: KxN, ldb=N, tile BK x BN
            int r = tid >> 4;
            int c = (tid & 15) * 4;
            float4 bb = *(const float4*)(B + (size_t)(k0 + r) * N + n0 + c);
            *(float4*)&Bs[r][c] = bb;
        } else {
            // NT: B is NxK, ldb=K, tile BN x BK, store transposed
            int r = tid >> 2;            // 0..63 (n)
            int c = (tid & 3) * 4;       // 0,4,8,12 (k)
            float4 bb = *(const float4*)(B + (size_t)(n0 + r) * K + k0 + c);
            Bs[c + 0][r] = bb.x; Bs[c + 1][r] = bb.y;
            Bs[c + 2][r] = bb.z; Bs[c + 3][r] = bb.w;
        }
        __syncthreads();

        #pragma unroll
        for (int kk = 0; kk < BK; kk++) {
            float4 av = *(const float4*)&As[kk][ty * 4];
            float4 bv = *(const float4*)&Bs[kk][tx * 4];
            float a[4] = {av.x, av.y, av.z, av.w};
            float b[4] = {bv.x, bv.y, bv.z, bv.w};
            #pragma unroll
            for (int i = 0; i < 4; i++)
                #pragma unroll
                for (int j = 0; j < 4; j++)
                    acc[i][j] += a[i] * b[j];
        }
        __syncthreads();
    }

    // ---- epilogue ----
    #pragma unroll
    for (int i = 0; i < 4; i++) {
        int m = m0 + ty * 4 + i;
        float bval = HAS_BIAS ? bias[m] : 0.f;
        size_t off = (size_t)m * N + n0 + tx * 4;
        float v0 = acc[i][0] * alpha + bval;
        float v1 = acc[i][1] * alpha + bval;
        float v2 = acc[i][2] * alpha + bval;
        float v3 = acc[i][3] * alpha + bval;
        if (HAS_RES) {
            float4 rr = *(const float4*)(res + off);
            v0 += rr.x; v1 += rr.y; v2 += rr.z; v3 += rr.w;
        }
        float4 r4 = {v0, v1, v2, v3};
        *(float4*)(C + off) = r4;
    }
}

// ---------------------------------------------------------------------------
// Row softmax over 4096 keys. One block (256 thr) per row; 16 values/thread
// held in registers -> exactly one global read + one global write per element.
// ---------------------------------------------------------------------------
__global__ void __launch_bounds__(256) softmax_kernel(float* __restrict__ S)
{
    float* p = S + (size_t)blockIdx.x * HW;
    const int tid = threadIdx.x;

    float v[16];
    float mx = -1e30f;
    #pragma unroll
    for (int i = 0; i < 16; i++) {
        v[i] = p[tid + i * 256];
        mx = fmaxf(mx, v[i]);
    }
    __shared__ float sh[8];
    #pragma unroll
    for (int o = 16; o; o >>= 1) mx = fmaxf(mx, __shfl_down_sync(0xffffffffu, mx, o));
    if ((tid & 31) == 0) sh[tid >> 5] = mx;
    __syncthreads();
    __shared__ float s_mx;
    if (tid == 0) {
        float m = sh[0];
        #pragma unroll
        for (int i = 1; i < 8; i++) m = fmaxf(m, sh[i]);
        s_mx = m;
    }
    __syncthreads();
    mx = s_mx;

    float sum = 0.f;
    #pragma unroll
    for (int i = 0; i < 16; i++) {
        v[i] = __expf(v[i] - mx);
        sum += v[i];
    }
    #pragma unroll
    for (int o = 16; o; o >>= 1) sum += __shfl_down_sync(0xffffffffu, sum, o);
    if ((tid & 31) == 0) sh[tid >> 5] = sum;
    __syncthreads();
    __shared__ float s_sum;
    if (tid == 0) {
        float s = 0.f;
        #pragma unroll
        for (int i = 0; i < 8; i++) s += sh[i];
        s_sum = s;
    }
    __syncthreads();
    const float inv = 1.f / s_sum;

    #pragma unroll
    for (int i = 0; i < 16; i++)
        p[tid + i * 256] = v[i] * inv;
}

// ---------------------------------------------------------------------------
extern "C" void kernel_launch(void* const* d_in, const int* in_sizes, int n_in,
                              void* d_out, int out_size)
{
    const float* x  = (const float*)d_in[0];
    const float* gw = (const float*)d_in[1];
    const float* gb = (const float*)d_in[2];
    const float* wq = (const float*)d_in[3];
    const float* bq = (const float*)d_in[4];
    const float* wk = (const float*)d_in[5];
    const float* bk = (const float*)d_in[6];
    const float* wv = (const float*)d_in[7];
    const float* bv = (const float*)d_in[8];
    const float* wp = (const float*)d_in[9];
    const float* bp = (const float*)d_in[10];
    float* out = (float*)d_out;

    float *hn, *q, *k, *v, *o, *s;
    cudaGetSymbolAddress((void**)&hn, g_hn);
    cudaGetSymbolAddress((void**)&q,  g_q);
    cudaGetSymbolAddress((void**)&k,  g_k);
    cudaGetSymbolAddress((void**)&v,  g_v);
    cudaGetSymbolAddress((void**)&o,  g_o);
    cudaGetSymbolAddress((void**)&s,  g_s);

    const long sBat = (long)C_ * HW;    // per-batch stride for [c, N] tensors
    const long sSc  = (long)HW * HW;    // per-batch stride for scores

    // 1) GroupNorm
    gn_kernel<<<B_ * G_, 256>>>(x, gw, gb);

    // 2) Q, K, V = W(512x512) * hn(512x4096) + b  (per batch)
    dim3 gQKV(HW / BN, C_ / BM, B_);
    gemm_kernel<0, true, false><<<gQKV, 256>>>(wq, hn, q, bq, nullptr,
                                               C_, HW, C_, 0, sBat, sBat, 1.f);
    gemm_kernel<0, true, false><<<gQKV, 256>>>(wk, hn, k, bk, nullptr,
                                               C_, HW, C_, 0, sBat, sBat, 1.f);
    gemm_kernel<0, true, false><<<gQKV, 256>>>(wv, hn, v, bv, nullptr,
                                               C_, HW, C_, 0, sBat, sBat, 1.f);

    // 3) scores = scale * Q^T K   (TN: A=q as [K=512 x M=4096], B=k)
    const float scale = 1.f / sqrtf((float)C_);
    dim3 gS(HW / BN, HW / BM, B_);
    gemm_kernel<1, false, false><<<gS, 256>>>(q, k, s, nullptr, nullptr,
                                              HW, HW, C_, sBat, sBat, sSc, scale);

    // 4) softmax over keys (rows of s)
    softmax_kernel<<<B_ * HW, 256>>>(s);

    // 5) o = V(512x4096) * P^T(4096x4096)   (NT)
    dim3 gO(HW / BN, C_ / BM, B_);
    gemm_kernel<2, false, false><<<gO, 256>>>(v, s, o, nullptr, nullptr,
                                              C_, HW, HW, sBat, sSc, sBat, 1.f);

    // 6) out = x + Wp * o + bp   (NN with bias + residual)
    gemm_kernel<0, true, true><<<gO, 256>>>(wp, o, out, bp, x,
                                            C_, HW, C_, 0, sBat, sBat, 1.f);
}

// round 5
// speedup vs baseline: 6.4771x; 6.4771x over previous
#include <cuda_runtime.h>
#include <cuda_bf16.h>
#include <math.h>
#include <stdint.h>

#define B_  4
#define C_  512
#define HW  4096
#define G_  32
#define CPG 16

typedef __nv_bfloat16 bf16;

// ---------------- scratch (__device__ globals; no allocation allowed) -------
__device__ __align__(256) bf16  g_hn[(size_t)B_ * C_ * HW];
__device__ __align__(256) bf16  g_qT[(size_t)B_ * HW * C_];   // [b][pix][c]
__device__ __align__(256) bf16  g_k [(size_t)B_ * C_ * HW];   // [b][c][pix]
__device__ __align__(256) bf16  g_vT[(size_t)B_ * HW * C_];   // [b][pix][c]
__device__ __align__(256) float g_s [(size_t)B_ * HW * HW];   // fp32 scores
__device__ __align__(256) bf16  g_p [(size_t)B_ * HW * HW];   // bf16 probs
__device__ __align__(256) bf16  g_oT[(size_t)B_ * HW * C_];   // [b][pix][c]
__device__ __align__(256) bf16  g_wq[C_ * C_];
__device__ __align__(256) bf16  g_wk[C_ * C_];
__device__ __align__(256) bf16  g_wv[C_ * C_];
__device__ __align__(256) bf16  g_wpT[C_ * C_];               // [cin][cout]

// ---------------- ptx helpers ----------------------------------------------
__device__ __forceinline__ uint32_t smem_u32(const void* p) {
    return (uint32_t)__cvta_generic_to_shared(p);
}
__device__ __forceinline__ void cp16(uint32_t d, const void* s) {
    asm volatile("cp.async.cg.shared.global [%0], [%1], 16;" :: "r"(d), "l"(s));
}
__device__ __forceinline__ void cp_commit() {
    asm volatile("cp.async.commit_group;");
}
template<int N> __device__ __forceinline__ void cp_wait() {
    asm volatile("cp.async.wait_group %0;" :: "n"(N));
}
__device__ __forceinline__ void ldsm4(uint32_t* r, uint32_t a) {
    asm volatile("ldmatrix.sync.aligned.m8n8.x4.shared.b16 {%0,%1,%2,%3}, [%4];"
        : "=r"(r[0]), "=r"(r[1]), "=r"(r[2]), "=r"(r[3]) : "r"(a));
}
__device__ __forceinline__ void ldsm4t(uint32_t* r, uint32_t a) {
    asm volatile("ldmatrix.sync.aligned.m8n8.x4.trans.shared.b16 {%0,%1,%2,%3}, [%4];"
        : "=r"(r[0]), "=r"(r[1]), "=r"(r[2]), "=r"(r[3]) : "r"(a));
}
__device__ __forceinline__ void mma16816(float* c, const uint32_t* a, const uint32_t* b) {
    asm volatile("mma.sync.aligned.m16n8k16.row.col.f32.bf16.bf16.f32 "
        "{%0,%1,%2,%3}, {%4,%5,%6,%7}, {%8,%9}, {%0,%1,%2,%3};"
        : "+f"(c[0]), "+f"(c[1]), "+f"(c[2]), "+f"(c[3])
        : "r"(a[0]), "r"(a[1]), "r"(a[2]), "r"(a[3]), "r"(b[0]), "r"(b[1]));
}

// ---------------- weight convert (+ transpose wp) ---------------------------
__global__ void __launch_bounds__(256) convw_kernel(
    const float* __restrict__ wq, const float* __restrict__ wk,
    const float* __restrict__ wv, const float* __restrict__ wp)
{
    int i = blockIdx.x * 256 + threadIdx.x;        // 0 .. 512*512-1
    g_wq[i] = __float2bfloat16(wq[i]);
    g_wk[i] = __float2bfloat16(wk[i]);
    g_wv[i] = __float2bfloat16(wv[i]);
    int r = i >> 9, c = i & 511;                   // wp[r][c] -> wpT[c][r]
    g_wpT[(size_t)c * C_ + r] = __float2bfloat16(wp[i]);
}

// ---------------- GroupNorm -> bf16 hn --------------------------------------
__global__ void __launch_bounds__(256) gn_kernel(const float* __restrict__ x,
                                                 const float* __restrict__ gw,
                                                 const float* __restrict__ gb)
{
    const int bg = blockIdx.x;          // 0..127
    const int b = bg / G_, g = bg % G_;
    const size_t base = ((size_t)b * C_ + (size_t)g * CPG) * HW;
    const float* xp = x + base;
    bf16* op = g_hn + base;
    const int NELE = CPG * HW;          // 65536
    const int tid = threadIdx.x;

    float s = 0.f, ss = 0.f;
    for (int i = tid; i < NELE; i += 256) {
        float v = xp[i];
        s += v; ss += v * v;
    }
    __shared__ float shs[8], shss[8];
    #pragma unroll
    for (int o = 16; o; o >>= 1) {
        s  += __shfl_down_sync(0xffffffffu, s,  o);
        ss += __shfl_down_sync(0xffffffffu, ss, o);
    }
    if ((tid & 31) == 0) { shs[tid >> 5] = s; shss[tid >> 5] = ss; }
    __syncthreads();
    __shared__ float s_mu, s_rs;
    if (tid == 0) {
        float S = 0.f, SS = 0.f;
        #pragma unroll
        for (int i = 0; i < 8; i++) { S += shs[i]; SS += shss[i]; }
        float mu  = S / (float)NELE;
        float var = SS / (float)NELE - mu * mu;
        s_mu = mu;
        s_rs = rsqrtf(var + 1e-6f);
    }
    __syncthreads();
    const float mu = s_mu, rs = s_rs;
    for (int i = tid; i < NELE; i += 256) {
        int ch = g * CPG + (i >> 12);
        op[i] = __float2bfloat16((xp[i] - mu) * rs * gw[ch] + gb[ch]);
    }
}

// ---------------- bf16 tensor-core GEMM -------------------------------------
// C[M,N] (fp32 accum) = A[M,K] (row-major bf16, lda) * B[K,N] (row-major bf16, ldb)
// EPI 0: bf16 store C[m*ldo+n], + bias[m] (optional)
// EPI 1: bf16 store transposed C[n*ldo+m], + bias[m] (optional)
// EPI 2: fp32 store C[m*ldo+n] * alpha
// EPI 3: fp32 store transposed C[n*ldo+m] + bias[n] + res[n*ldo+m]
// Requires M%128==0, N%128==0, K%32==0. 256 threads.
#define BM 128
#define BN 128
#define BK 32
#define PADA 8
#define PADB 8

template<int EPI>
__global__ void __launch_bounds__(256) mm_kernel(
    const bf16* __restrict__ Ag, const bf16* __restrict__ Bg,
    void* __restrict__ Cout, const float* __restrict__ bias,
    const float* __restrict__ res,
    int M, int N, int K, int lda, int ldb, int ldo,
    long sA, long sB, long sC, float alpha)
{
    const int bz = blockIdx.z;
    Ag += (size_t)bz * sA;
    Bg += (size_t)bz * sB;

    __shared__ bf16 As[2][BM][BK + PADA];
    __shared__ bf16 Bs[2][BK][BN + PADB];

    const int tid  = threadIdx.x;
    const int m0   = blockIdx.y * BM;
    const int n0   = blockIdx.x * BN;
    const int warp = tid >> 5, lane = tid & 31;
    const int wm   = (warp >> 2) * 64;    // 2 warps along m
    const int wn   = (warp & 3) * 32;     // 4 warps along n

    float acc[4][4][4];
    #pragma unroll
    for (int i = 0; i < 4; i++)
        #pragma unroll
        for (int j = 0; j < 4; j++)
            #pragma unroll
            for (int q = 0; q < 4; q++) acc[i][j][q] = 0.f;

    // loads: 512 16B-chunks each for A and B, 2 per thread
    auto load_stage = [&](int st, int k0) {
        #pragma unroll
        for (int it = 0; it < 2; it++) {
            int c = tid + it * 256;
            int ra = c >> 2, ka = (c & 3) * 8;                       // A: 128 x 32
            cp16(smem_u32(&As[st][ra][ka]),
                 Ag + (size_t)(m0 + ra) * lda + k0 + ka);
            int rb = c >> 4, nb = (c & 15) * 8;                      // B: 32 x 128
            cp16(smem_u32(&Bs[st][rb][nb]),
                 Bg + (size_t)(k0 + rb) * ldb + n0 + nb);
        }
    };

    load_stage(0, 0);
    cp_commit();

    const int KT = K / BK;
    for (int kt = 0; kt < KT; kt++) {
        const int st = kt & 1;
        cp_wait<0>();
        __syncthreads();                 // stage st visible; prev compute done
        if (kt + 1 < KT) { load_stage(st ^ 1, (kt + 1) * BK); cp_commit(); }

        #pragma unroll
        for (int kk = 0; kk < BK; kk += 16) {
            uint32_t a[4][4], b[2][4];
            #pragma unroll
            for (int mt = 0; mt < 4; mt++) {
                int row = wm + mt * 16 + (lane & 15);
                int col = kk + (lane >> 4) * 8;
                ldsm4(a[mt], smem_u32(&As[st][row][col]));
            }
            #pragma unroll
            for (int nt2 = 0; nt2 < 2; nt2++) {
                int row = kk + (lane & 15);
                int col = wn + nt2 * 16 + (lane >> 4) * 8;
                ldsm4t(b[nt2], smem_u32(&Bs[st][row][col]));
            }
            #pragma unroll
            for (int mt = 0; mt < 4; mt++)
                #pragma unroll
                for (int nt = 0; nt < 4; nt++)
                    mma16816(acc[mt][nt], a[mt], &b[nt >> 1][(nt & 1) * 2]);
        }
        __syncthreads();                 // done reading stage st before reload
    }

    // ---- epilogue ----
    const int g  = lane >> 2;
    const int tg = lane & 3;
    #pragma unroll
    for (int mt = 0; mt < 4; mt++) {
        int r = m0 + wm + mt * 16 + g;
        #pragma unroll
        for (int nt = 0; nt < 4; nt++) {
            int c = n0 + wn + nt * 8 + tg * 2;
            const float* a = acc[mt][nt];
            if constexpr (EPI == 0) {
                bf16* C = (bf16*)Cout + (size_t)bz * sC;
                float b0 = bias ? bias[r]     : 0.f;
                float b1 = bias ? bias[r + 8] : 0.f;
                __nv_bfloat162 t0, t1;
                t0.x = __float2bfloat16(a[0] + b0); t0.y = __float2bfloat16(a[1] + b0);
                t1.x = __float2bfloat16(a[2] + b1); t1.y = __float2bfloat16(a[3] + b1);
                *(__nv_bfloat162*)(C + (size_t)r * ldo + c)       = t0;
                *(__nv_bfloat162*)(C + (size_t)(r + 8) * ldo + c) = t1;
            } else if constexpr (EPI == 1) {
                bf16* C = (bf16*)Cout + (size_t)bz * sC;
                float b0 = bias ? bias[r]     : 0.f;
                float b1 = bias ? bias[r + 8] : 0.f;
                C[(size_t)c * ldo + r]           = __float2bfloat16(a[0] + b0);
                C[(size_t)(c + 1) * ldo + r]     = __float2bfloat16(a[1] + b0);
                C[(size_t)c * ldo + r + 8]       = __float2bfloat16(a[2] + b1);
                C[(size_t)(c + 1) * ldo + r + 8] = __float2bfloat16(a[3] + b1);
            } else if constexpr (EPI == 2) {
                float* C = (float*)Cout + (size_t)bz * sC;
                float2 t0 = {a[0] * alpha, a[1] * alpha};
                float2 t1 = {a[2] * alpha, a[3] * alpha};
                *(float2*)(C + (size_t)r * ldo + c)       = t0;
                *(float2*)(C + (size_t)(r + 8) * ldo + c) = t1;
            } else {
                float* C = (float*)Cout + (size_t)bz * sC;
                const float* R = res + (size_t)bz * sC;
                float b0 = bias[c], b1 = bias[c + 1];
                C[(size_t)c * ldo + r]           = a[0] + b0 + R[(size_t)c * ldo + r];
                C[(size_t)(c + 1) * ldo + r]     = a[1] + b1 + R[(size_t)(c + 1) * ldo + r];
                C[(size_t)c * ldo + r + 8]       = a[2] + b0 + R[(size_t)c * ldo + r + 8];
                C[(size_t)(c + 1) * ldo + r + 8] = a[3] + b1 + R[(size_t)(c + 1) * ldo + r + 8];
            }
        }
    }
}

// ---------------- softmax: fp32 in -> bf16 out ------------------------------
__global__ void __launch_bounds__(256) softmax_kernel(const float* __restrict__ S,
                                                      bf16* __restrict__ P)
{
    const float* p = S + (size_t)blockIdx.x * HW;
    bf16* po = P + (size_t)blockIdx.x * HW;
    const int tid = threadIdx.x;

    float v[16];
    float mx = -1e30f;
    #pragma unroll
    for (int i = 0; i < 16; i++) {
        v[i] = p[tid + i * 256];
        mx = fmaxf(mx, v[i]);
    }
    __shared__ float sh[8];
    #pragma unroll
    for (int o = 16; o; o >>= 1) mx = fmaxf(mx, __shfl_down_sync(0xffffffffu, mx, o));
    if ((tid & 31) == 0) sh[tid >> 5] = mx;
    __syncthreads();
    __shared__ float s_mx;
    if (tid == 0) {
        float m = sh[0];
        #pragma unroll
        for (int i = 1; i < 8; i++) m = fmaxf(m, sh[i]);
        s_mx = m;
    }
    __syncthreads();
    mx = s_mx;

    float sum = 0.f;
    #pragma unroll
    for (int i = 0; i < 16; i++) {
        v[i] = __expf(v[i] - mx);
        sum += v[i];
    }
    #pragma unroll
    for (int o = 16; o; o >>= 1) sum += __shfl_down_sync(0xffffffffu, sum, o);
    if ((tid & 31) == 0) sh[tid >> 5] = sum;
    __syncthreads();
    __shared__ float s_sum;
    if (tid == 0) {
        float s = 0.f;
        #pragma unroll
        for (int i = 0; i < 8; i++) s += sh[i];
        s_sum = s;
    }
    __syncthreads();
    const float inv = 1.f / s_sum;

    #pragma unroll
    for (int i = 0; i < 16; i++)
        po[tid + i * 256] = __float2bfloat16(v[i] * inv);
}

// ---------------------------------------------------------------------------
extern "C" void kernel_launch(void* const* d_in, const int* in_sizes, int n_in,
                              void* d_out, int out_size)
{
    const float* x  = (const float*)d_in[0];
    const float* gw = (const float*)d_in[1];
    const float* gb = (const float*)d_in[2];
    const float* wq = (const float*)d_in[3];
    const float* bq = (const float*)d_in[4];
    const float* wk = (const float*)d_in[5];
    const float* bk = (const float*)d_in[6];
    const float* wv = (const float*)d_in[7];
    const float* bv = (const float*)d_in[8];
    const float* wp = (const float*)d_in[9];
    const float* bp = (const float*)d_in[10];
    float* out = (float*)d_out;

    bf16 *hn, *qT, *k, *vT, *p, *oT;
    float* s;
    cudaGetSymbolAddress((void**)&hn, g_hn);
    cudaGetSymbolAddress((void**)&qT, g_qT);
    cudaGetSymbolAddress((void**)&k,  g_k);
    cudaGetSymbolAddress((void**)&vT, g_vT);
    cudaGetSymbolAddress((void**)&s,  g_s);
    cudaGetSymbolAddress((void**)&p,  g_p);
    cudaGetSymbolAddress((void**)&oT, g_oT);
    bf16 *wqb, *wkb, *wvb, *wptb;
    cudaGetSymbolAddress((void**)&wqb,  g_wq);
    cudaGetSymbolAddress((void**)&wkb,  g_wk);
    cudaGetSymbolAddress((void**)&wvb,  g_wv);
    cudaGetSymbolAddress((void**)&wptb, g_wpT);

    const long sAct = (long)C_ * HW;     // batch stride for [c,pix] / [pix,c]
    const long sSc  = (long)HW * HW;

    convw_kernel<<<(C_ * C_) / 256, 256>>>(wq, wk, wv, wp);
    gn_kernel<<<B_ * G_, 256>>>(x, gw, gb);

    // Q,K,V: [cout=512, pix=4096] = W[512,512] * hn[512,4096]
    dim3 gq(HW / BN, C_ / BM, B_);
    mm_kernel<1><<<gq, 256>>>(wqb, hn, qT, bq, nullptr,
                              C_, HW, C_, C_, HW, C_, 0, sAct, sAct, 1.f);
    mm_kernel<0><<<gq, 256>>>(wkb, hn, k,  bk, nullptr,
                              C_, HW, C_, C_, HW, HW, 0, sAct, sAct, 1.f);
    mm_kernel<1><<<gq, 256>>>(wvb, hn, vT, bv, nullptr,
                              C_, HW, C_, C_, HW, C_, 0, sAct, sAct, 1.f);

    // scores[i,j] = scale * qT[i,:] . k[:,j]
    const float scale = 1.f / sqrtf((float)C_);
    dim3 gs(HW / BN, HW / BM, B_);
    mm_kernel<2><<<gs, 256>>>(qT, k, s, nullptr, nullptr,
                              HW, HW, C_, C_, HW, HW, (long)HW * C_, sAct, sSc, scale);

    softmax_kernel<<<B_ * HW, 256>>>(s, p);

    // oT[i,c] = P[i,:] . vT[:,c]
    dim3 go(C_ / BN, HW / BM, B_);
    mm_kernel<0><<<go, 256>>>(p, vT, oT, nullptr, nullptr,
                              HW, C_, HW, HW, C_, C_, sSc, (long)HW * C_, (long)HW * C_, 1.f);

    // out[cout,pix] = x + oT[pix,:] . wpT[:,cout] + bp
    mm_kernel<3><<<go, 256>>>(oT, wptb, out, bp, x,
                              HW, C_, C_, C_, C_, HW, (long)HW * C_, 0, sAct, 1.f);
}

// round 6
// speedup vs baseline: 7.1458x; 1.1033x over previous
#include <cuda_runtime.h>
#include <cuda_bf16.h>
#include <math.h>
#include <stdint.h>

#define B_  4
#define C_  512
#define HW  4096
#define G_  32
#define CPG 16

typedef __nv_bfloat16 bf16;

// ---------------- scratch (__device__ globals; no allocation allowed) -------
__device__ __align__(256) bf16  g_hn[(size_t)B_ * C_ * HW];
__device__ __align__(256) bf16  g_qT[(size_t)B_ * HW * C_];   // [b][pix][c]
__device__ __align__(256) bf16  g_k [(size_t)B_ * C_ * HW];   // [b][c][pix]
__device__ __align__(256) bf16  g_vT[(size_t)B_ * HW * C_];   // [b][pix][c]
__device__ __align__(256) bf16  g_p [(size_t)B_ * HW * HW];   // bf16 scores->probs (in-place)
__device__ __align__(256) bf16  g_oT[(size_t)B_ * HW * C_];   // [b][pix][c]
__device__ __align__(256) bf16  g_wq[C_ * C_];
__device__ __align__(256) bf16  g_wk[C_ * C_];
__device__ __align__(256) bf16  g_wv[C_ * C_];
__device__ __align__(256) bf16  g_wpT[C_ * C_];               // [cin][cout]

// ---------------- ptx helpers ----------------------------------------------
__device__ __forceinline__ uint32_t smem_u32(const void* p) {
    return (uint32_t)__cvta_generic_to_shared(p);
}
__device__ __forceinline__ void cp16(uint32_t d, const void* s) {
    asm volatile("cp.async.cg.shared.global [%0], [%1], 16;" :: "r"(d), "l"(s));
}
__device__ __forceinline__ void cp_commit() {
    asm volatile("cp.async.commit_group;");
}
template<int N> __device__ __forceinline__ void cp_wait() {
    asm volatile("cp.async.wait_group %0;" :: "n"(N));
}
__device__ __forceinline__ void ldsm4(uint32_t* r, uint32_t a) {
    asm volatile("ldmatrix.sync.aligned.m8n8.x4.shared.b16 {%0,%1,%2,%3}, [%4];"
        : "=r"(r[0]), "=r"(r[1]), "=r"(r[2]), "=r"(r[3]) : "r"(a));
}
__device__ __forceinline__ void ldsm4t(uint32_t* r, uint32_t a) {
    asm volatile("ldmatrix.sync.aligned.m8n8.x4.trans.shared.b16 {%0,%1,%2,%3}, [%4];"
        : "=r"(r[0]), "=r"(r[1]), "=r"(r[2]), "=r"(r[3]) : "r"(a));
}
__device__ __forceinline__ void mma16816(float* c, const uint32_t* a, const uint32_t* b) {
    asm volatile("mma.sync.aligned.m16n8k16.row.col.f32.bf16.bf16.f32 "
        "{%0,%1,%2,%3}, {%4,%5,%6,%7}, {%8,%9}, {%0,%1,%2,%3};"
        : "+f"(c[0]), "+f"(c[1]), "+f"(c[2]), "+f"(c[3])
        : "r"(a[0]), "r"(a[1]), "r"(a[2]), "r"(a[3]), "r"(b[0]), "r"(b[1]));
}

// ---------------- weight convert (+ transpose wp) ---------------------------
__global__ void __launch_bounds__(256) convw_kernel(
    const float* __restrict__ wq, const float* __restrict__ wk,
    const float* __restrict__ wv, const float* __restrict__ wp)
{
    int i = blockIdx.x * 256 + threadIdx.x;        // 0 .. 512*512-1
    g_wq[i] = __float2bfloat16(wq[i]);
    g_wk[i] = __float2bfloat16(wk[i]);
    g_wv[i] = __float2bfloat16(wv[i]);
    int r = i >> 9, c = i & 511;                   // wp[r][c] -> wpT[c][r]
    g_wpT[(size_t)c * C_ + r] = __float2bfloat16(wp[i]);
}

// ---------------- GroupNorm -> bf16 hn --------------------------------------
__global__ void __launch_bounds__(256) gn_kernel(const float* __restrict__ x,
                                                 const float* __restrict__ gw,
                                                 const float* __restrict__ gb)
{
    const int bg = blockIdx.x;          // 0..127
    const int b = bg / G_, g = bg % G_;
    const size_t base = ((size_t)b * C_ + (size_t)g * CPG) * HW;
    const float* xp = x + base;
    bf16* op = g_hn + base;
    const int NELE = CPG * HW;          // 65536
    const int tid = threadIdx.x;

    float s = 0.f, ss = 0.f;
    for (int i = tid; i < NELE; i += 256) {
        float v = xp[i];
        s += v; ss += v * v;
    }
    __shared__ float shs[8], shss[8];
    #pragma unroll
    for (int o = 16; o; o >>= 1) {
        s  += __shfl_down_sync(0xffffffffu, s,  o);
        ss += __shfl_down_sync(0xffffffffu, ss, o);
    }
    if ((tid & 31) == 0) { shs[tid >> 5] = s; shss[tid >> 5] = ss; }
    __syncthreads();
    __shared__ float s_mu, s_rs;
    if (tid == 0) {
        float S = 0.f, SS = 0.f;
        #pragma unroll
        for (int i = 0; i < 8; i++) { S += shs[i]; SS += shss[i]; }
        float mu  = S / (float)NELE;
        float var = SS / (float)NELE - mu * mu;
        s_mu = mu;
        s_rs = rsqrtf(var + 1e-6f);
    }
    __syncthreads();
    const float mu = s_mu, rs = s_rs;
    for (int i = tid; i < NELE; i += 256) {
        int ch = g * CPG + (i >> 12);
        op[i] = __float2bfloat16((xp[i] - mu) * rs * gw[ch] + gb[ch]);
    }
}

// ---------------- bf16 tensor-core GEMM (3-stage cp.async ring) -------------
// C[M,N] (fp32 accum) = A[M,K] (row-major bf16, lda) * B[K,N] (row-major bf16, ldb)
// EPI 0: bf16 store C[m*ldo+n], + bias[m] (optional)
// EPI 1: bf16 store transposed C[n*ldo+m], + bias[m] (optional)
// EPI 2: bf16 store C[m*ldo+n] * alpha
// EPI 3: fp32 store transposed C[n*ldo+m] + bias[n] + res[n*ldo+m]
// Requires M%128==0, N%128==0, K%32==0, K/32 >= 2. 256 threads.
#define BM 128
#define BN 128
#define BK 32
#define LDA_S (BK + 8)       // 40
#define LDB_S (BN + 8)       // 136
#define ST_A  (BM * LDA_S)   // 5120 elems per stage
#define ST_B  (BK * LDB_S)   // 4352 elems per stage
#define NSTG  3
#define SMEM_BYTES ((NSTG * (ST_A + ST_B)) * 2)   // 56832

template<int EPI>
__global__ void __launch_bounds__(256, 2) mm_kernel(
    const bf16* __restrict__ Ag, const bf16* __restrict__ Bg,
    void* __restrict__ Cout, const float* __restrict__ bias,
    const float* __restrict__ res,
    int M, int N, int K, int lda, int ldb, int ldo,
    long sA, long sB, long sC, float alpha)
{
    const int bz = blockIdx.z;
    Ag += (size_t)bz * sA;
    Bg += (size_t)bz * sB;

    extern __shared__ bf16 sm[];
    bf16* Asm = sm;                    // [NSTG][BM][LDA_S]
    bf16* Bsm = sm + NSTG * ST_A;      // [NSTG][BK][LDB_S]

    const int tid  = threadIdx.x;
    const int m0   = blockIdx.y * BM;
    const int n0   = blockIdx.x * BN;
    const int warp = tid >> 5, lane = tid & 31;
    const int wm   = (warp >> 2) * 64;    // 2 warps along m
    const int wn   = (warp & 3) * 32;     // 4 warps along n

    float acc[4][4][4];
    #pragma unroll
    for (int i = 0; i < 4; i++)
        #pragma unroll
        for (int j = 0; j < 4; j++)
            #pragma unroll
            for (int q = 0; q < 4; q++) acc[i][j][q] = 0.f;

    // per-stage loads: A 128x32, B 32x128; 512 16B-chunks each, 2 per thread
    auto load_stage = [&](int st, int k0) {
        bf16* As = Asm + st * ST_A;
        bf16* Bs = Bsm + st * ST_B;
        #pragma unroll
        for (int it = 0; it < 2; it++) {
            int c = tid + it * 256;
            int ra = c >> 2, ka = (c & 3) * 8;
            cp16(smem_u32(As + ra * LDA_S + ka),
                 Ag + (size_t)(m0 + ra) * lda + k0 + ka);
            int rb = c >> 4, nb = (c & 15) * 8;
            cp16(smem_u32(Bs + rb * LDB_S + nb),
                 Bg + (size_t)(k0 + rb) * ldb + n0 + nb);
        }
    };

    load_stage(0, 0);      cp_commit();
    load_stage(1, BK);     cp_commit();

    const int KT = K / BK;
    for (int kt = 0; kt < KT; kt++) {
        const int st = kt % NSTG;
        cp_wait<1>();                       // stage st complete (≤1 group pending)
        __syncthreads();                    // + everyone done reading stage (kt+2)%NSTG
        if (kt + 2 < KT) load_stage((kt + 2) % NSTG, (kt + 2) * BK);
        cp_commit();                        // commit every iter (empty ok) to keep numbering

        const bf16* As = Asm + st * ST_A;
        const bf16* Bs = Bsm + st * ST_B;
        #pragma unroll
        for (int kk = 0; kk < BK; kk += 16) {
            uint32_t a[4][4], b[2][4];
            #pragma unroll
            for (int mt = 0; mt < 4; mt++) {
                int row = wm + mt * 16 + (lane & 15);
                int col = kk + (lane >> 4) * 8;
                ldsm4(a[mt], smem_u32(As + row * LDA_S + col));
            }
            #pragma unroll
            for (int nt2 = 0; nt2 < 2; nt2++) {
                int row = kk + (lane & 15);
                int col = wn + nt2 * 16 + (lane >> 4) * 8;
                ldsm4t(b[nt2], smem_u32(Bs + row * LDB_S + col));
            }
            #pragma unroll
            for (int mt = 0; mt < 4; mt++)
                #pragma unroll
                for (int nt = 0; nt < 4; nt++)
                    mma16816(acc[mt][nt], a[mt], &b[nt >> 1][(nt & 1) * 2]);
        }
    }

    // ---- epilogue ----
    const int g  = lane >> 2;
    const int tg = lane & 3;
    #pragma unroll
    for (int mt = 0; mt < 4; mt++) {
        int r = m0 + wm + mt * 16 + g;
        #pragma unroll
        for (int nt = 0; nt < 4; nt++) {
            int c = n0 + wn + nt * 8 + tg * 2;
            const float* a = acc[mt][nt];
            if constexpr (EPI == 0) {
                bf16* C = (bf16*)Cout + (size_t)bz * sC;
                float b0 = bias ? bias[r]     : 0.f;
                float b1 = bias ? bias[r + 8] : 0.f;
                __nv_bfloat162 t0, t1;
                t0.x = __float2bfloat16(a[0] + b0); t0.y = __float2bfloat16(a[1] + b0);
                t1.x = __float2bfloat16(a[2] + b1); t1.y = __float2bfloat16(a[3] + b1);
                *(__nv_bfloat162*)(C + (size_t)r * ldo + c)       = t0;
                *(__nv_bfloat162*)(C + (size_t)(r + 8) * ldo + c) = t1;
            } else if constexpr (EPI == 1) {
                bf16* C = (bf16*)Cout + (size_t)bz * sC;
                float b0 = bias ? bias[r]     : 0.f;
                float b1 = bias ? bias[r + 8] : 0.f;
                C[(size_t)c * ldo + r]           = __float2bfloat16(a[0] + b0);
                C[(size_t)(c + 1) * ldo + r]     = __float2bfloat16(a[1] + b0);
                C[(size_t)c * ldo + r + 8]       = __float2bfloat16(a[2] + b1);
                C[(size_t)(c + 1) * ldo + r + 8] = __float2bfloat16(a[3] + b1);
            } else if constexpr (EPI == 2) {
                bf16* C = (bf16*)Cout + (size_t)bz * sC;
                __nv_bfloat162 t0, t1;
                t0.x = __float2bfloat16(a[0] * alpha); t0.y = __float2bfloat16(a[1] * alpha);
                t1.x = __float2bfloat16(a[2] * alpha); t1.y = __float2bfloat16(a[3] * alpha);
                *(__nv_bfloat162*)(C + (size_t)r * ldo + c)       = t0;
                *(__nv_bfloat162*)(C + (size_t)(r + 8) * ldo + c) = t1;
            } else {
                float* C = (float*)Cout + (size_t)bz * sC;
                const float* R = res + (size_t)bz * sC;
                float b0 = bias[c], b1 = bias[c + 1];
                C[(size_t)c * ldo + r]           = a[0] + b0 + R[(size_t)c * ldo + r];
                C[(size_t)(c + 1) * ldo + r]     = a[1] + b1 + R[(size_t)(c + 1) * ldo + r];
                C[(size_t)c * ldo + r + 8]       = a[2] + b0 + R[(size_t)c * ldo + r + 8];
                C[(size_t)(c + 1) * ldo + r + 8] = a[3] + b1 + R[(size_t)(c + 1) * ldo + r + 8];
            }
        }
    }
}

// ---------------- softmax in-place on bf16 scores ---------------------------
__global__ void __launch_bounds__(256) softmax_kernel(bf16* __restrict__ S)
{
    __nv_bfloat162* p = (__nv_bfloat162*)(S + (size_t)blockIdx.x * HW);
    const int tid = threadIdx.x;

    float2 v[8];
    float mx = -1e30f;
    #pragma unroll
    for (int i = 0; i < 8; i++) {
        v[i] = __bfloat1622float2(p[tid + i * 256]);
        mx = fmaxf(mx, fmaxf(v[i].x, v[i].y));
    }
    __shared__ float sh[8];
    #pragma unroll
    for (int o = 16; o; o >>= 1) mx = fmaxf(mx, __shfl_down_sync(0xffffffffu, mx, o));
    if ((tid & 31) == 0) sh[tid >> 5] = mx;
    __syncthreads();
    __shared__ float s_mx;
    if (tid == 0) {
        float m = sh[0];
        #pragma unroll
        for (int i = 1; i < 8; i++) m = fmaxf(m, sh[i]);
        s_mx = m;
    }
    __syncthreads();
    mx = s_mx;

    float sum = 0.f;
    #pragma unroll
    for (int i = 0; i < 8; i++) {
        v[i].x = __expf(v[i].x - mx);
        v[i].y = __expf(v[i].y - mx);
        sum += v[i].x + v[i].y;
    }
    #pragma unroll
    for (int o = 16; o; o >>= 1) sum += __shfl_down_sync(0xffffffffu, sum, o);
    if ((tid & 31) == 0) sh[tid >> 5] = sum;
    __syncthreads();
    __shared__ float s_sum;
    if (tid == 0) {
        float s = 0.f;
        #pragma unroll
        for (int i = 0; i < 8; i++) s += sh[i];
        s_sum = s;
    }
    __syncthreads();
    const float inv = 1.f / s_sum;

    #pragma unroll
    for (int i = 0; i < 8; i++) {
        __nv_bfloat162 t;
        t.x = __float2bfloat16(v[i].x * inv);
        t.y = __float2bfloat16(v[i].y * inv);
        p[tid + i * 256] = t;
    }
}

// ---------------------------------------------------------------------------
extern "C" void kernel_launch(void* const* d_in, const int* in_sizes, int n_in,
                              void* d_out, int out_size)
{
    const float* x  = (const float*)d_in[0];
    const float* gw = (const float*)d_in[1];
    const float* gb = (const float*)d_in[2];
    const float* wq = (const float*)d_in[3];
    const float* bq = (const float*)d_in[4];
    const float* wk = (const float*)d_in[5];
    const float* bk = (const float*)d_in[6];
    const float* wv = (const float*)d_in[7];
    const float* bv = (const float*)d_in[8];
    const float* wp = (const float*)d_in[9];
    const float* bp = (const float*)d_in[10];
    float* out = (float*)d_out;

    cudaFuncSetAttribute(mm_kernel<0>, cudaFuncAttributeMaxDynamicSharedMemorySize, SMEM_BYTES);
    cudaFuncSetAttribute(mm_kernel<1>, cudaFuncAttributeMaxDynamicSharedMemorySize, SMEM_BYTES);
    cudaFuncSetAttribute(mm_kernel<2>, cudaFuncAttributeMaxDynamicSharedMemorySize, SMEM_BYTES);
    cudaFuncSetAttribute(mm_kernel<3>, cudaFuncAttributeMaxDynamicSharedMemorySize, SMEM_BYTES);

    bf16 *hn, *qT, *k, *vT, *p, *oT;
    cudaGetSymbolAddress((void**)&hn, g_hn);
    cudaGetSymbolAddress((void**)&qT, g_qT);
    cudaGetSymbolAddress((void**)&k,  g_k);
    cudaGetSymbolAddress((void**)&vT, g_vT);
    cudaGetSymbolAddress((void**)&p,  g_p);
    cudaGetSymbolAddress((void**)&oT, g_oT);
    bf16 *wqb, *wkb, *wvb, *wptb;
    cudaGetSymbolAddress((void**)&wqb,  g_wq);
    cudaGetSymbolAddress((void**)&wkb,  g_wk);
    cudaGetSymbolAddress((void**)&wvb,  g_wv);
    cudaGetSymbolAddress((void**)&wptb, g_wpT);

    const long sAct = (long)C_ * HW;     // batch stride for [c,pix] / [pix,c]
    const long sSc  = (long)HW * HW;

    convw_kernel<<<(C_ * C_) / 256, 256>>>(wq, wk, wv, wp);
    gn_kernel<<<B_ * G_, 256>>>(x, gw, gb);

    // Q,K,V: [cout=512, pix=4096] = W[512,512] * hn[512,4096]
    dim3 gq(HW / BN, C_ / BM, B_);
    mm_kernel<1><<<gq, 256, SMEM_BYTES>>>(wqb, hn, qT, bq, nullptr,
                              C_, HW, C_, C_, HW, C_, 0, sAct, sAct, 1.f);
    mm_kernel<0><<<gq, 256, SMEM_BYTES>>>(wkb, hn, k,  bk, nullptr,
                              C_, HW, C_, C_, HW, HW, 0, sAct, sAct, 1.f);
    mm_kernel<1><<<gq, 256, SMEM_BYTES>>>(wvb, hn, vT, bv, nullptr,
                              C_, HW, C_, C_, HW, C_, 0, sAct, sAct, 1.f);

    // scores[i,j] = scale * qT[i,:] . k[:,j]   -> bf16, straight into P buffer
    const float scale = 1.f / sqrtf((float)C_);
    dim3 gs(HW / BN, HW / BM, B_);
    mm_kernel<2><<<gs, 256, SMEM_BYTES>>>(qT, k, p, nullptr, nullptr,
                              HW, HW, C_, C_, HW, HW, (long)HW * C_, sAct, sSc, scale);

    // softmax over keys, in place
    softmax_kernel<<<B_ * HW, 256>>>(p);

    // oT[i,c] = P[i,:] . vT[:,c]
    dim3 go(C_ / BN, HW / BM, B_);
    mm_kernel<0><<<go, 256, SMEM_BYTES>>>(p, vT, oT, nullptr, nullptr,
                              HW, C_, HW, HW, C_, C_, sSc, (long)HW * C_, (long)HW * C_, 1.f);

    // out[cout,pix] = x + oT[pix,:] . wpT[:,cout] + bp
    mm_kernel<3><<<go, 256, SMEM_BYTES>>>(oT, wptb, out, bp, x,
                              HW, C_, C_, C_, C_, HW, (long)HW * C_, 0, sAct, 1.f);
}

// round 7
// speedup vs baseline: 7.2017x; 1.0078x over previous
#include <cuda_runtime.h>
#include <cuda_bf16.h>
#include <math.h>
#include <stdint.h>

#define B_  4
#define C_  512
#define HW  4096
#define G_  32
#define CPG 16

typedef __nv_bfloat16 bf16;

// ---------------- scratch (__device__ globals; no allocation allowed) -------
__device__ __align__(256) bf16  g_hn[(size_t)B_ * C_ * HW];
__device__ __align__(256) bf16  g_qT[(size_t)B_ * HW * C_];   // [b][pix][c]
__device__ __align__(256) bf16  g_k [(size_t)B_ * C_ * HW];   // [b][c][pix]
__device__ __align__(256) bf16  g_vT[(size_t)B_ * HW * C_];   // [b][pix][c]
__device__ __align__(256) bf16  g_p [(size_t)B_ * HW * HW];   // bf16 scores->probs (in-place)
__device__ __align__(256) bf16  g_oT[(size_t)B_ * HW * C_];   // [b][pix][c]
__device__ __align__(256) bf16  g_wq[C_ * C_];
__device__ __align__(256) bf16  g_wk[C_ * C_];
__device__ __align__(256) bf16  g_wv[C_ * C_];
__device__ __align__(256) bf16  g_wpT[C_ * C_];               // [cin][cout]

// ---------------- ptx helpers ----------------------------------------------
__device__ __forceinline__ uint32_t smem_u32(const void* p) {
    return (uint32_t)__cvta_generic_to_shared(p);
}
__device__ __forceinline__ void cp16(uint32_t d, const void* s) {
    asm volatile("cp.async.cg.shared.global [%0], [%1], 16;" :: "r"(d), "l"(s));
}
__device__ __forceinline__ void cp_commit() {
    asm volatile("cp.async.commit_group;");
}
template<int N> __device__ __forceinline__ void cp_wait() {
    asm volatile("cp.async.wait_group %0;" :: "n"(N));
}
__device__ __forceinline__ void ldsm4(uint32_t* r, uint32_t a) {
    asm volatile("ldmatrix.sync.aligned.m8n8.x4.shared.b16 {%0,%1,%2,%3}, [%4];"
        : "=r"(r[0]), "=r"(r[1]), "=r"(r[2]), "=r"(r[3]) : "r"(a));
}
__device__ __forceinline__ void ldsm4t(uint32_t* r, uint32_t a) {
    asm volatile("ldmatrix.sync.aligned.m8n8.x4.trans.shared.b16 {%0,%1,%2,%3}, [%4];"
        : "=r"(r[0]), "=r"(r[1]), "=r"(r[2]), "=r"(r[3]) : "r"(a));
}
__device__ __forceinline__ void mma16816(float* c, const uint32_t* a, const uint32_t* b) {
    asm volatile("mma.sync.aligned.m16n8k16.row.col.f32.bf16.bf16.f32 "
        "{%0,%1,%2,%3}, {%4,%5,%6,%7}, {%8,%9}, {%0,%1,%2,%3};"
        : "+f"(c[0]), "+f"(c[1]), "+f"(c[2]), "+f"(c[3])
        : "r"(a[0]), "r"(a[1]), "r"(a[2]), "r"(a[3]), "r"(b[0]), "r"(b[1]));
}

// ---------------- weight convert (+ transpose wp) ---------------------------
__global__ void __launch_bounds__(256) convw_kernel(
    const float* __restrict__ wq, const float* __restrict__ wk,
    const float* __restrict__ wv, const float* __restrict__ wp)
{
    int i = blockIdx.x * 256 + threadIdx.x;        // 0 .. 512*512-1
    g_wq[i] = __float2bfloat16(wq[i]);
    g_wk[i] = __float2bfloat16(wk[i]);
    g_wv[i] = __float2bfloat16(wv[i]);
    int r = i >> 9, c = i & 511;                   // wp[r][c] -> wpT[c][r]
    g_wpT[(size_t)c * C_ + r] = __float2bfloat16(wp[i]);
}

// ---------------- GroupNorm -> bf16 hn --------------------------------------
__global__ void __launch_bounds__(256) gn_kernel(const float* __restrict__ x,
                                                 const float* __restrict__ gw,
                                                 const float* __restrict__ gb)
{
    const int bg = blockIdx.x;          // 0..127
    const int b = bg / G_, g = bg % G_;
    const size_t base = ((size_t)b * C_ + (size_t)g * CPG) * HW;
    const float* xp = x + base;
    bf16* op = g_hn + base;
    const int NELE = CPG * HW;          // 65536
    const int tid = threadIdx.x;

    float s = 0.f, ss = 0.f;
    for (int i = tid; i < NELE; i += 256) {
        float v = xp[i];
        s += v; ss += v * v;
    }
    __shared__ float shs[8], shss[8];
    #pragma unroll
    for (int o = 16; o; o >>= 1) {
        s  += __shfl_down_sync(0xffffffffu, s,  o);
        ss += __shfl_down_sync(0xffffffffu, ss, o);
    }
    if ((tid & 31) == 0) { shs[tid >> 5] = s; shss[tid >> 5] = ss; }
    __syncthreads();
    __shared__ float s_mu, s_rs;
    if (tid == 0) {
        float S = 0.f, SS = 0.f;
        #pragma unroll
        for (int i = 0; i < 8; i++) { S += shs[i]; SS += shss[i]; }
        float mu  = S / (float)NELE;
        float var = SS / (float)NELE - mu * mu;
        s_mu = mu;
        s_rs = rsqrtf(var + 1e-6f);
    }
    __syncthreads();
    const float mu = s_mu, rs = s_rs;
    for (int i = tid; i < NELE; i += 256) {
        int ch = g * CPG + (i >> 12);
        op[i] = __float2bfloat16((xp[i] - mu) * rs * gw[ch] + gb[ch]);
    }
}

// ---------------- bf16 tensor-core GEMM (3-stage ring, frag pipelined) ------
// C[M,N] (fp32 accum) = A[M,K] (row-major bf16, lda) * B[K,N] (row-major bf16, ldb)
// EPI 0: bf16 store C[m*ldo+n], + bias[m] (optional)
// EPI 1: bf16 store transposed C[n*ldo+m], + bias[m] (optional)
// EPI 2: bf16 store C[m*ldo+n] * alpha
// EPI 3: fp32 store transposed C[n*ldo+m] + bias[n] + res[n*ldo+m]
// Requires M%128==0, N%128==0, K%64==0, K/64 >= 2. 256 threads.
#define BM 128
#define BN 128
#define BK 64
#define LDA_S (BK + 8)       // 72
#define LDB_S (BN + 8)       // 136
#define ST_A  (BM * LDA_S)   // 9216 elems per stage
#define ST_B  (BK * LDB_S)   // 8704 elems per stage
#define NSTG  3
#define SMEM_BYTES ((NSTG * (ST_A + ST_B)) * 2)   // 107520

template<int EPI>
__global__ void __launch_bounds__(256, 2) mm_kernel(
    const bf16* __restrict__ Ag, const bf16* __restrict__ Bg,
    void* __restrict__ Cout, const float* __restrict__ bias,
    const float* __restrict__ res,
    int M, int N, int K, int lda, int ldb, int ldo,
    long sA, long sB, long sC, float alpha)
{
    const int bz = blockIdx.z;
    Ag += (size_t)bz * sA;
    Bg += (size_t)bz * sB;

    extern __shared__ bf16 sm[];
    bf16* Asm = sm;                    // [NSTG][BM][LDA_S]
    bf16* Bsm = sm + NSTG * ST_A;      // [NSTG][BK][LDB_S]

    const int tid  = threadIdx.x;
    const int m0   = blockIdx.y * BM;
    const int n0   = blockIdx.x * BN;
    const int warp = tid >> 5, lane = tid & 31;
    const int wm   = (warp >> 2) * 64;    // 2 warps along m
    const int wn   = (warp & 3) * 32;     // 4 warps along n

    float acc[4][4][4];
    #pragma unroll
    for (int i = 0; i < 4; i++)
        #pragma unroll
        for (int j = 0; j < 4; j++)
            #pragma unroll
            for (int q = 0; q < 4; q++) acc[i][j][q] = 0.f;

    // per-stage loads: A 128x64, B 64x128; 1024 16B-chunks each, 4+4 per thread
    auto load_stage = [&](int st, int k0) {
        bf16* As = Asm + st * ST_A;
        bf16* Bs = Bsm + st * ST_B;
        #pragma unroll
        for (int it = 0; it < 4; it++) {
            int c = tid + it * 256;
            int ra = c >> 3, ka = (c & 7) * 8;        // A: 128 rows x 64 cols
            cp16(smem_u32(As + ra * LDA_S + ka),
                 Ag + (size_t)(m0 + ra) * lda + k0 + ka);
            int rb = c >> 4, nb = (c & 15) * 8;       // B: 64 rows x 128 cols
            cp16(smem_u32(Bs + rb * LDB_S + nb),
                 Bg + (size_t)(k0 + rb) * ldb + n0 + nb);
        }
    };

    load_stage(0, 0);      cp_commit();
    load_stage(1, BK);     cp_commit();

    // ping-pong register fragments
    uint32_t afr[2][4][4], bfr[2][2][4];
    const int a_row = (lane & 15);
    const int a_col = (lane >> 4) * 8;

    const int KT = K / BK;
    for (int kt = 0; kt < KT; kt++) {
        const int st = kt % NSTG;
        cp_wait<1>();                       // stage st complete (≤1 group pending)
        __syncthreads();                    // all threads see stage st; stage (kt+2)%NSTG free
        if (kt + 2 < KT) load_stage((kt + 2) % NSTG, (kt + 2) * BK);
        cp_commit();                        // commit every iter (empty ok) to keep numbering

        const bf16* As = Asm + st * ST_A;
        const bf16* Bs = Bsm + st * ST_B;

        // load fragment group 0 (kk = 0)
        #pragma unroll
        for (int mt = 0; mt < 4; mt++)
            ldsm4(afr[0][mt], smem_u32(As + (wm + mt * 16 + a_row) * LDA_S + a_col));
        #pragma unroll
        for (int nt2 = 0; nt2 < 2; nt2++)
            ldsm4t(bfr[0][nt2], smem_u32(Bs + a_row * LDB_S + wn + nt2 * 16 + a_col));

        #pragma unroll
        for (int g = 0; g < 4; g++) {       // 4 groups of k=16 within BK=64
            const int cur = g & 1;
            if (g < 3) {                    // prefetch group g+1 before MMAs of g
                const int kk = (g + 1) * 16;
                #pragma unroll
                for (int mt = 0; mt < 4; mt++)
                    ldsm4(afr[cur ^ 1][mt],
                          smem_u32(As + (wm + mt * 16 + a_row) * LDA_S + kk + a_col));
                #pragma unroll
                for (int nt2 = 0; nt2 < 2; nt2++)
                    ldsm4t(bfr[cur ^ 1][nt2],
                           smem_u32(Bs + (kk + a_row) * LDB_S + wn + nt2 * 16 + a_col));
            }
            #pragma unroll
            for (int mt = 0; mt < 4; mt++)
                #pragma unroll
                for (int nt = 0; nt < 4; nt++)
                    mma16816(acc[mt][nt], afr[cur][mt], &bfr[cur][nt >> 1][(nt & 1) * 2]);
        }
    }

    // ---- epilogue ----
    const int g  = lane >> 2;
    const int tg = lane & 3;
    #pragma unroll
    for (int mt = 0; mt < 4; mt++) {
        int r = m0 + wm + mt * 16 + g;
        #pragma unroll
        for (int nt = 0; nt < 4; nt++) {
            int c = n0 + wn + nt * 8 + tg * 2;
            const float* a = acc[mt][nt];
            if constexpr (EPI == 0) {
                bf16* C = (bf16*)Cout + (size_t)bz * sC;
                float b0 = bias ? bias[r]     : 0.f;
                float b1 = bias ? bias[r + 8] : 0.f;
                __nv_bfloat162 t0, t1;
                t0.x = __float2bfloat16(a[0] + b0); t0.y = __float2bfloat16(a[1] + b0);
                t1.x = __float2bfloat16(a[2] + b1); t1.y = __float2bfloat16(a[3] + b1);
                *(__nv_bfloat162*)(C + (size_t)r * ldo + c)       = t0;
                *(__nv_bfloat162*)(C + (size_t)(r + 8) * ldo + c) = t1;
            } else if constexpr (EPI == 1) {
                bf16* C = (bf16*)Cout + (size_t)bz * sC;
                float b0 = bias ? bias[r]     : 0.f;
                float b1 = bias ? bias[r + 8] : 0.f;
                C[(size_t)c * ldo + r]           = __float2bfloat16(a[0] + b0);
                C[(size_t)(c + 1) * ldo + r]     = __float2bfloat16(a[1] + b0);
                C[(size_t)c * ldo + r + 8]       = __float2bfloat16(a[2] + b1);
                C[(size_t)(c + 1) * ldo + r + 8] = __float2bfloat16(a[3] + b1);
            } else if constexpr (EPI == 2) {
                bf16* C = (bf16*)Cout + (size_t)bz * sC;
                __nv_bfloat162 t0, t1;
                t0.x = __float2bfloat16(a[0] * alpha); t0.y = __float2bfloat16(a[1] * alpha);
                t1.x = __float2bfloat16(a[2] * alpha); t1.y = __float2bfloat16(a[3] * alpha);
                *(__nv_bfloat162*)(C + (size_t)r * ldo + c)       = t0;
                *(__nv_bfloat162*)(C + (size_t)(r + 8) * ldo + c) = t1;
            } else {
                float* C = (float*)Cout + (size_t)bz * sC;
                const float* R = res + (size_t)bz * sC;
                float b0 = bias[c], b1 = bias[c + 1];
                C[(size_t)c * ldo + r]           = a[0] + b0 + R[(size_t)c * ldo + r];
                C[(size_t)(c + 1) * ldo + r]     = a[1] + b1 + R[(size_t)(c + 1) * ldo + r];
                C[(size_t)c * ldo + r + 8]       = a[2] + b0 + R[(size_t)c * ldo + r + 8];
                C[(size_t)(c + 1) * ldo + r + 8] = a[3] + b1 + R[(size_t)(c + 1) * ldo + r + 8];
            }
        }
    }
}

// ---------------- softmax in-place on bf16 scores ---------------------------
__global__ void __launch_bounds__(256) softmax_kernel(bf16* __restrict__ S)
{
    __nv_bfloat162* p = (__nv_bfloat162*)(S + (size_t)blockIdx.x * HW);
    const int tid = threadIdx.x;

    float2 v[8];
    float mx = -1e30f;
    #pragma unroll
    for (int i = 0; i < 8; i++) {
        v[i] = __bfloat1622float2(p[tid + i * 256]);
        mx = fmaxf(mx, fmaxf(v[i].x, v[i].y));
    }
    __shared__ float sh[8];
    #pragma unroll
    for (int o = 16; o; o >>= 1) mx = fmaxf(mx, __shfl_down_sync(0xffffffffu, mx, o));
    if ((tid & 31) == 0) sh[tid >> 5] = mx;
    __syncthreads();
    __shared__ float s_mx;
    if (tid == 0) {
        float m = sh[0];
        #pragma unroll
        for (int i = 1; i < 8; i++) m = fmaxf(m, sh[i]);
        s_mx = m;
    }
    __syncthreads();
    mx = s_mx;

    float sum = 0.f;
    #pragma unroll
    for (int i = 0; i < 8; i++) {
        v[i].x = __expf(v[i].x - mx);
        v[i].y = __expf(v[i].y - mx);
        sum += v[i].x + v[i].y;
    }
    #pragma unroll
    for (int o = 16; o; o >>= 1) sum += __shfl_down_sync(0xffffffffu, sum, o);
    if ((tid & 31) == 0) sh[tid >> 5] = sum;
    __syncthreads();
    __shared__ float s_sum;
    if (tid == 0) {
        float s = 0.f;
        #pragma unroll
        for (int i = 0; i < 8; i++) s += sh[i];
        s_sum = s;
    }
    __syncthreads();
    const float inv = 1.f / s_sum;

    #pragma unroll
    for (int i = 0; i < 8; i++) {
        __nv_bfloat162 t;
        t.x = __float2bfloat16(v[i].x * inv);
        t.y = __float2bfloat16(v[i].y * inv);
        p[tid + i * 256] = t;
    }
}

// ---------------------------------------------------------------------------
extern "C" void kernel_launch(void* const* d_in, const int* in_sizes, int n_in,
                              void* d_out, int out_size)
{
    const float* x  = (const float*)d_in[0];
    const float* gw = (const float*)d_in[1];
    const float* gb = (const float*)d_in[2];
    const float* wq = (const float*)d_in[3];
    const float* bq = (const float*)d_in[4];
    const float* wk = (const float*)d_in[5];
    const float* bk = (const float*)d_in[6];
    const float* wv = (const float*)d_in[7];
    const float* bv = (const float*)d_in[8];
    const float* wp = (const float*)d_in[9];
    const float* bp = (const float*)d_in[10];
    float* out = (float*)d_out;

    cudaFuncSetAttribute(mm_kernel<0>, cudaFuncAttributeMaxDynamicSharedMemorySize, SMEM_BYTES);
    cudaFuncSetAttribute(mm_kernel<1>, cudaFuncAttributeMaxDynamicSharedMemorySize, SMEM_BYTES);
    cudaFuncSetAttribute(mm_kernel<2>, cudaFuncAttributeMaxDynamicSharedMemorySize, SMEM_BYTES);
    cudaFuncSetAttribute(mm_kernel<3>, cudaFuncAttributeMaxDynamicSharedMemorySize, SMEM_BYTES);

    bf16 *hn, *qT, *k, *vT, *p, *oT;
    cudaGetSymbolAddress((void**)&hn, g_hn);
    cudaGetSymbolAddress((void**)&qT, g_qT);
    cudaGetSymbolAddress((void**)&k,  g_k);
    cudaGetSymbolAddress((void**)&vT, g_vT);
    cudaGetSymbolAddress((void**)&p,  g_p);
    cudaGetSymbolAddress((void**)&oT, g_oT);
    bf16 *wqb, *wkb, *wvb, *wptb;
    cudaGetSymbolAddress((void**)&wqb,  g_wq);
    cudaGetSymbolAddress((void**)&wkb,  g_wk);
    cudaGetSymbolAddress((void**)&wvb,  g_wv);
    cudaGetSymbolAddress((void**)&wptb, g_wpT);

    const long sAct = (long)C_ * HW;     // batch stride for [c,pix] / [pix,c]
    const long sSc  = (long)HW * HW;

    convw_kernel<<<(C_ * C_) / 256, 256>>>(wq, wk, wv, wp);
    gn_kernel<<<B_ * G_, 256>>>(x, gw, gb);

    // Q,K,V: [cout=512, pix=4096] = W[512,512] * hn[512,4096]
    dim3 gq(HW / BN, C_ / BM, B_);
    mm_kernel<1><<<gq, 256, SMEM_BYTES>>>(wqb, hn, qT, bq, nullptr,
                              C_, HW, C_, C_, HW, C_, 0, sAct, sAct, 1.f);
    mm_kernel<0><<<gq, 256, SMEM_BYTES>>>(wkb, hn, k,  bk, nullptr,
                              C_, HW, C_, C_, HW, HW, 0, sAct, sAct, 1.f);
    mm_kernel<1><<<gq, 256, SMEM_BYTES>>>(wvb, hn, vT, bv, nullptr,
                              C_, HW, C_, C_, HW, C_, 0, sAct, sAct, 1.f);

    // scores[i,j] = scale * qT[i,:] . k[:,j]   -> bf16, straight into P buffer
    const float scale = 1.f / sqrtf((float)C_);
    dim3 gs(HW / BN, HW / BM, B_);
    mm_kernel<2><<<gs, 256, SMEM_BYTES>>>(qT, k, p, nullptr, nullptr,
                              HW, HW, C_, C_, HW, HW, (long)HW * C_, sAct, sSc, scale);

    // softmax over keys, in place
    softmax_kernel<<<B_ * HW, 256>>>(p);

    // oT[i,c] = P[i,:] . vT[:,c]
    dim3 go(C_ / BN, HW / BM, B_);
    mm_kernel<0><<<go, 256, SMEM_BYTES>>>(p, vT, oT, nullptr, nullptr,
                              HW, C_, HW, HW, C_, C_, sSc, (long)HW * C_, (long)HW * C_, 1.f);

    // out[cout,pix] = x + oT[pix,:] . wpT[:,cout] + bp
    mm_kernel<3><<<go, 256, SMEM_BYTES>>>(oT, wptb, out, bp, x,
                              HW, C_, C_, C_, C_, HW, (long)HW * C_, 0, sAct, 1.f);
}